// round 2
// baseline (speedup 1.0000x reference)
#include <cuda_runtime.h>

#define D 64
#define MAX_NODES 150016
#define MAX_EDGES 2100000

// Static scratch (allocation-free rule).
__device__ float g_x[(size_t)MAX_NODES * D];    // layer ping
__device__ float g_y[(size_t)MAX_NODES * D];    // layer pong
__device__ float g_acc[(size_t)MAX_NODES * D];  // running sum of layer embeddings
__device__ int   g_cnt[MAX_NODES];              // per-dst edge counts
__device__ int   g_off[MAX_NODES + 1];          // CSR offsets
__device__ int   g_cur[MAX_NODES];              // scatter cursors
__device__ int2  g_edge[MAX_EDGES];             // dst-grouped (src, w-bits)

__global__ void zero_cnt_kernel(int n) {
    int i = blockIdx.x * blockDim.x + threadIdx.x;
    if (i < n) g_cnt[i] = 0;
}

// Concatenate user/item embeddings into g_x and g_acc.
__global__ void init_kernel(const float* __restrict__ ue,
                            const float* __restrict__ ie,
                            int n_user_f, int n4) {
    int i = blockIdx.x * blockDim.x + threadIdx.x;   // float4 index
    if (i >= n4) return;
    int f = i << 2;
    float4 v = (f < n_user_f) ? ((const float4*)ue)[i]
                              : ((const float4*)ie)[i - (n_user_f >> 2)];
    ((float4*)g_x)[i]   = v;
    ((float4*)g_acc)[i] = v;
}

__global__ void hist_kernel(const int* __restrict__ dst, int n_edges) {
    int e = blockIdx.x * blockDim.x + threadIdx.x;
    if (e < n_edges) atomicAdd(&g_cnt[dst[e]], 1);
}

// Single-block exclusive scan of g_cnt -> g_off / g_cur (chunk-per-thread).
__global__ void scan_kernel(int n) {
    __shared__ int sh[1024];
    int tid = threadIdx.x;
    int per = (n + 1023) >> 10;
    int beg = tid * per;
    int end = min(beg + per, n);
    int s = 0;
    for (int i = beg; i < end; i++) s += g_cnt[i];
    sh[tid] = s;
    __syncthreads();
    for (int off = 1; off < 1024; off <<= 1) {
        int v = (tid >= off) ? sh[tid - off] : 0;
        __syncthreads();
        sh[tid] += v;
        __syncthreads();
    }
    int run = sh[tid] - s;                 // exclusive prefix for this chunk
    for (int i = beg; i < end; i++) {
        g_off[i] = run;
        g_cur[i] = run;
        run += g_cnt[i];
    }
    if (tid == 1023) g_off[n] = sh[1023];
}

__global__ void scatter_kernel(const int* __restrict__ src,
                               const int* __restrict__ dst,
                               const float* __restrict__ w, int n_edges) {
    int e = blockIdx.x * blockDim.x + threadIdx.x;
    if (e >= n_edges) return;
    int d = dst[e];
    int pos = atomicAdd(&g_cur[d], 1);
    g_edge[pos] = make_int2(src[e], __float_as_int(w[e]));
}

// CSR SpMM: 16 threads per dst node, float4 per thread. Register-accumulated,
// one plain 256B row store, acc += fused. No atomics.
__global__ void spmm_csr_kernel(int n_nodes, int flip) {
    const float* __restrict__ x = flip ? g_y : g_x;
    float*                    y = flip ? g_x : g_y;
    int t = blockIdx.x * blockDim.x + threadIdx.x;
    int node = t >> 4;
    if (node >= n_nodes) return;
    int c = (t & 15) << 2;                 // float offset within row: 0..60
    int beg = g_off[node];
    int end = g_off[node + 1];
    float4 a = make_float4(0.f, 0.f, 0.f, 0.f);
    int i = beg;
    for (; i + 2 <= end; i += 2) {         // 2x unroll for gather MLP
        int2 p0 = g_edge[i];
        int2 p1 = g_edge[i + 1];
        float4 v0 = *(const float4*)(x + (size_t)p0.x * D + c);
        float4 v1 = *(const float4*)(x + (size_t)p1.x * D + c);
        float w0 = __int_as_float(p0.y);
        float w1 = __int_as_float(p1.y);
        a.x += w0 * v0.x + w1 * v1.x;
        a.y += w0 * v0.y + w1 * v1.y;
        a.z += w0 * v0.z + w1 * v1.z;
        a.w += w0 * v0.w + w1 * v1.w;
    }
    if (i < end) {
        int2 p = g_edge[i];
        float4 v = *(const float4*)(x + (size_t)p.x * D + c);
        float ww = __int_as_float(p.y);
        a.x += ww * v.x; a.y += ww * v.y; a.z += ww * v.z; a.w += ww * v.w;
    }
    size_t idx = (size_t)node * D + c;
    *(float4*)(y + idx) = a;               // full overwrite (zero-degree -> 0)
    float4 ac = *(const float4*)(g_acc + idx);
    ac.x += a.x; ac.y += a.y; ac.z += a.z; ac.w += a.w;
    *(float4*)(g_acc + idx) = ac;
}

// One warp per (user, item) pair: float2 per lane, shfl reduction.
// Both rows carry an implicit 1/4 scale -> fold 1/16 into the dot product.
__global__ void score_kernel(const int* __restrict__ users,
                             const int* __restrict__ items,
                             float* __restrict__ out, int B, int n_users) {
    int g    = blockIdx.x * blockDim.x + threadIdx.x;
    int pair = g >> 5;
    int lane = threadIdx.x & 31;
    if (pair >= B) return;
    int ur = users[pair];
    int ir = n_users + items[pair];
    float2 u = ((const float2*)(g_acc + (size_t)ur * D))[lane];
    float2 v = ((const float2*)(g_acc + (size_t)ir * D))[lane];
    float s = u.x * v.x + u.y * v.y;
    #pragma unroll
    for (int o = 16; o; o >>= 1) s += __shfl_xor_sync(0xffffffffu, s, o);
    if (lane == 0) out[pair] = s * (1.0f / 16.0f);
}

extern "C" void kernel_launch(void* const* d_in, const int* in_sizes, int n_in,
                              void* d_out, int out_size) {
    const float* ue    = (const float*)d_in[0];
    const float* ie    = (const float*)d_in[1];
    const int*   esrc  = (const int*)  d_in[2];
    const int*   edst  = (const int*)  d_in[3];
    const float* ew    = (const float*)d_in[4];
    const int*   users = (const int*)  d_in[5];
    const int*   items = (const int*)  d_in[6];

    int n_user_f  = in_sizes[0];
    int n_item_f  = in_sizes[1];
    int n_edges   = in_sizes[2];
    int B         = in_sizes[5];
    int n_total_f = n_user_f + n_item_f;
    int n_users   = n_user_f / D;
    int n_nodes   = n_total_f / D;
    int n4        = n_total_f >> 2;

    zero_cnt_kernel<<<(n_nodes + 255) / 256, 256>>>(n_nodes);
    init_kernel<<<(n4 + 255) / 256, 256>>>(ue, ie, n_user_f, n4);
    hist_kernel<<<(n_edges + 255) / 256, 256>>>(edst, n_edges);
    scan_kernel<<<1, 1024>>>(n_nodes);
    scatter_kernel<<<(n_edges + 255) / 256, 256>>>(esrc, edst, ew, n_edges);

    for (int l = 0; l < 3; l++) {
        long long t = (long long)n_nodes * 16;
        spmm_csr_kernel<<<(int)((t + 255) / 256), 256>>>(n_nodes, l & 1);
    }

    score_kernel<<<(B * 32 + 255) / 256, 256>>>(users, items, (float*)d_out,
                                                B, n_users);
}

// round 3
// speedup vs baseline: 1.8866x; 1.8866x over previous
#include <cuda_runtime.h>

#define D 64
#define MAX_NODES 150016
#define MAX_EDGES 2100000
#define SCAN_B 512
#define MAX_BLKS ((MAX_NODES + SCAN_B - 1) / SCAN_B)

// Static scratch (allocation-free rule).
__device__ float g_x[(size_t)MAX_NODES * D];    // layer ping
__device__ float g_y[(size_t)MAX_NODES * D];    // layer pong
__device__ float g_acc[(size_t)MAX_NODES * D];  // running sum of layer embeddings
__device__ int   g_cnt[MAX_NODES];              // per-dst edge counts
__device__ int   g_off[MAX_NODES + 1];          // CSR offsets
__device__ int   g_cur[MAX_NODES];              // scatter cursors
__device__ int   g_bsum[MAX_BLKS];              // per-block sums for scan
__device__ int2  g_edge[MAX_EDGES];             // dst-grouped (src, w-bits)

__global__ void zero_cnt_kernel(int n) {
    int i = blockIdx.x * blockDim.x + threadIdx.x;
    if (i < n) g_cnt[i] = 0;
}

// Concatenate user/item embeddings into g_x and g_acc.
__global__ void init_kernel(const float* __restrict__ ue,
                            const float* __restrict__ ie,
                            int n_user_f, int n4) {
    int i = blockIdx.x * blockDim.x + threadIdx.x;   // float4 index
    if (i >= n4) return;
    int f = i << 2;
    float4 v = (f < n_user_f) ? ((const float4*)ue)[i]
                              : ((const float4*)ie)[i - (n_user_f >> 2)];
    ((float4*)g_x)[i]   = v;
    ((float4*)g_acc)[i] = v;
}

__global__ void hist_kernel(const int* __restrict__ dst, int n_edges) {
    int e = blockIdx.x * blockDim.x + threadIdx.x;
    if (e < n_edges) atomicAdd(&g_cnt[dst[e]], 1);
}

// Block-wide inclusive scan of one int per thread (SCAN_B threads).
__device__ __forceinline__ int block_incl_scan(int v) {
    __shared__ int wsum[SCAN_B / 32];
    int lane = threadIdx.x & 31;
    int wid  = threadIdx.x >> 5;
    int x = v;
    #pragma unroll
    for (int o = 1; o < 32; o <<= 1) {
        int t = __shfl_up_sync(0xffffffffu, x, o);
        if (lane >= o) x += t;
    }
    if (lane == 31) wsum[wid] = x;
    __syncthreads();
    if (wid == 0) {
        int w = (lane < SCAN_B / 32) ? wsum[lane] : 0;
        #pragma unroll
        for (int o = 1; o < SCAN_B / 32; o <<= 1) {
            int t = __shfl_up_sync(0xffffffffu, w, o);
            if (lane >= o) w += t;
        }
        if (lane < SCAN_B / 32) wsum[lane] = w;
    }
    __syncthreads();
    return x + (wid ? wsum[wid - 1] : 0);
}

// Pass A: per-block scan; exclusive prefix -> g_off, block total -> g_bsum.
__global__ void scanA_kernel(int n) {
    int i = blockIdx.x * SCAN_B + threadIdx.x;
    int v = (i < n) ? g_cnt[i] : 0;
    int inc = block_incl_scan(v);
    if (i < n) g_off[i] = inc - v;
    if (threadIdx.x == SCAN_B - 1) g_bsum[blockIdx.x] = inc;
}

// Pass B: single block scans the block sums; also writes g_off[n] = total.
__global__ void scanB_kernel(int nblk, int n) {
    int v = (threadIdx.x < nblk) ? g_bsum[threadIdx.x] : 0;
    int inc = block_incl_scan(v);
    if (threadIdx.x < nblk) g_bsum[threadIdx.x] = inc - v;
    if (threadIdx.x == SCAN_B - 1) g_off[n] = inc;
}

// Pass C: add block offsets; mirror into scatter cursors.
__global__ void scanC_kernel(int n) {
    int i = blockIdx.x * SCAN_B + threadIdx.x;
    if (i < n) {
        int o = g_off[i] + g_bsum[blockIdx.x];
        g_off[i] = o;
        g_cur[i] = o;
    }
}

__global__ void scatter_kernel(const int* __restrict__ src,
                               const int* __restrict__ dst,
                               const float* __restrict__ w, int n_edges) {
    int e = blockIdx.x * blockDim.x + threadIdx.x;
    if (e >= n_edges) return;
    int d = dst[e];
    int pos = atomicAdd(&g_cur[d], 1);
    g_edge[pos] = make_int2(src[e], __float_as_int(w[e]));
}

// CSR SpMM: 16 threads per dst node, float4 per thread. Register-accumulated,
// one plain 256B row store, acc += fused. No atomics.
__global__ void spmm_csr_kernel(int n_nodes, int flip) {
    const float* __restrict__ x = flip ? g_y : g_x;
    float*                    y = flip ? g_x : g_y;
    int t = blockIdx.x * blockDim.x + threadIdx.x;
    int node = t >> 4;
    if (node >= n_nodes) return;
    int c = (t & 15) << 2;                 // float offset within row: 0..60
    int beg = g_off[node];
    int end = g_off[node + 1];
    float4 a = make_float4(0.f, 0.f, 0.f, 0.f);
    int i = beg;
    for (; i + 2 <= end; i += 2) {         // 2x unroll for gather MLP
        int2 p0 = g_edge[i];
        int2 p1 = g_edge[i + 1];
        float4 v0 = *(const float4*)(x + (size_t)p0.x * D + c);
        float4 v1 = *(const float4*)(x + (size_t)p1.x * D + c);
        float w0 = __int_as_float(p0.y);
        float w1 = __int_as_float(p1.y);
        a.x += w0 * v0.x + w1 * v1.x;
        a.y += w0 * v0.y + w1 * v1.y;
        a.z += w0 * v0.z + w1 * v1.z;
        a.w += w0 * v0.w + w1 * v1.w;
    }
    if (i < end) {
        int2 p = g_edge[i];
        float4 v = *(const float4*)(x + (size_t)p.x * D + c);
        float ww = __int_as_float(p.y);
        a.x += ww * v.x; a.y += ww * v.y; a.z += ww * v.z; a.w += ww * v.w;
    }
    size_t idx = (size_t)node * D + c;
    *(float4*)(y + idx) = a;               // full overwrite (zero-degree -> 0)
    float4 ac = *(const float4*)(g_acc + idx);
    ac.x += a.x; ac.y += a.y; ac.z += a.z; ac.w += a.w;
    *(float4*)(g_acc + idx) = ac;
}

// One warp per (user, item) pair: float2 per lane, shfl reduction.
// Both rows carry an implicit 1/4 scale -> fold 1/16 into the dot product.
__global__ void score_kernel(const int* __restrict__ users,
                             const int* __restrict__ items,
                             float* __restrict__ out, int B, int n_users) {
    int g    = blockIdx.x * blockDim.x + threadIdx.x;
    int pair = g >> 5;
    int lane = threadIdx.x & 31;
    if (pair >= B) return;
    int ur = users[pair];
    int ir = n_users + items[pair];
    float2 u = ((const float2*)(g_acc + (size_t)ur * D))[lane];
    float2 v = ((const float2*)(g_acc + (size_t)ir * D))[lane];
    float s = u.x * v.x + u.y * v.y;
    #pragma unroll
    for (int o = 16; o; o >>= 1) s += __shfl_xor_sync(0xffffffffu, s, o);
    if (lane == 0) out[pair] = s * (1.0f / 16.0f);
}

extern "C" void kernel_launch(void* const* d_in, const int* in_sizes, int n_in,
                              void* d_out, int out_size) {
    const float* ue    = (const float*)d_in[0];
    const float* ie    = (const float*)d_in[1];
    const int*   esrc  = (const int*)  d_in[2];
    const int*   edst  = (const int*)  d_in[3];
    const float* ew    = (const float*)d_in[4];
    const int*   users = (const int*)  d_in[5];
    const int*   items = (const int*)  d_in[6];

    int n_user_f  = in_sizes[0];
    int n_item_f  = in_sizes[1];
    int n_edges   = in_sizes[2];
    int B         = in_sizes[5];
    int n_total_f = n_user_f + n_item_f;
    int n_users   = n_user_f / D;
    int n_nodes   = n_total_f / D;
    int n4        = n_total_f >> 2;
    int nblk      = (n_nodes + SCAN_B - 1) / SCAN_B;

    zero_cnt_kernel<<<(n_nodes + 255) / 256, 256>>>(n_nodes);
    init_kernel<<<(n4 + 255) / 256, 256>>>(ue, ie, n_user_f, n4);
    hist_kernel<<<(n_edges + 255) / 256, 256>>>(edst, n_edges);
    scanA_kernel<<<nblk, SCAN_B>>>(n_nodes);
    scanB_kernel<<<1, SCAN_B>>>(nblk, n_nodes);
    scanC_kernel<<<nblk, SCAN_B>>>(n_nodes);
    scatter_kernel<<<(n_edges + 255) / 256, 256>>>(esrc, edst, ew, n_edges);

    for (int l = 0; l < 3; l++) {
        long long t = (long long)n_nodes * 16;
        spmm_csr_kernel<<<(int)((t + 255) / 256), 256>>>(n_nodes, l & 1);
    }

    score_kernel<<<(B * 32 + 255) / 256, 256>>>(users, items, (float*)d_out,
                                                B, n_users);
}

// round 6
// speedup vs baseline: 2.5941x; 1.3750x over previous
#include <cuda_runtime.h>

#define D 64
#define MAX_NODES 150016
#define MAX_EDGES 2100000
#define SCAN_B 512
#define MAX_BLKS ((MAX_NODES + SCAN_B - 1) / SCAN_B)

// Static scratch (allocation-free rule). Never passed from host as kernel
// args — kernels bind these symbols directly (host-side decay of __device__
// symbols is invalid; that was the R4 failure).
__device__ float g_x[(size_t)MAX_NODES * D];    // x0 concat, later overwritten by x2
__device__ float g_y[(size_t)MAX_NODES * D];    // x1
__device__ float g_b3[(size_t)MAX_NODES * D];   // x3 (valid only at sampled rows)
__device__ int   g_cnt[MAX_NODES];              // per-dst edge counts
__device__ int   g_off[MAX_NODES + 1];          // CSR offsets
__device__ int   g_cur[MAX_NODES];              // scatter cursors
__device__ int   g_bsum[MAX_BLKS];              // per-block sums for scan
__device__ int2  g_edge[MAX_EDGES];             // dst-grouped (src, w-bits)

__global__ void zero_cnt_kernel(int n) {
    int i = blockIdx.x * blockDim.x + threadIdx.x;
    if (i < n) g_cnt[i] = 0;
}

// Concatenate user/item embeddings into g_x (x0).
__global__ void init_kernel(const float* __restrict__ ue,
                            const float* __restrict__ ie,
                            int n_user_f, int n4) {
    int i = blockIdx.x * blockDim.x + threadIdx.x;   // float4 index
    if (i >= n4) return;
    int f = i << 2;
    float4 v = (f < n_user_f) ? ((const float4*)ue)[i]
                              : ((const float4*)ie)[i - (n_user_f >> 2)];
    ((float4*)g_x)[i] = v;
}

__global__ void hist_kernel(const int* __restrict__ dst, int n_edges) {
    int e = blockIdx.x * blockDim.x + threadIdx.x;
    if (e < n_edges) atomicAdd(&g_cnt[dst[e]], 1);
}

// Block-wide inclusive scan of one int per thread (SCAN_B threads).
__device__ __forceinline__ int block_incl_scan(int v) {
    __shared__ int wsum[SCAN_B / 32];
    int lane = threadIdx.x & 31;
    int wid  = threadIdx.x >> 5;
    int x = v;
    #pragma unroll
    for (int o = 1; o < 32; o <<= 1) {
        int t = __shfl_up_sync(0xffffffffu, x, o);
        if (lane >= o) x += t;
    }
    if (lane == 31) wsum[wid] = x;
    __syncthreads();
    if (wid == 0) {
        int w = (lane < SCAN_B / 32) ? wsum[lane] : 0;
        #pragma unroll
        for (int o = 1; o < SCAN_B / 32; o <<= 1) {
            int t = __shfl_up_sync(0xffffffffu, w, o);
            if (lane >= o) w += t;
        }
        if (lane < SCAN_B / 32) wsum[lane] = w;
    }
    __syncthreads();
    return x + (wid ? wsum[wid - 1] : 0);
}

// Pass A: per-block scan; exclusive prefix -> g_off, block total -> g_bsum.
__global__ void scanA_kernel(int n) {
    int i = blockIdx.x * SCAN_B + threadIdx.x;
    int v = (i < n) ? g_cnt[i] : 0;
    int inc = block_incl_scan(v);
    if (i < n) g_off[i] = inc - v;
    if (threadIdx.x == SCAN_B - 1) g_bsum[blockIdx.x] = inc;
}

// Pass B: single block scans the block sums; also writes g_off[n] = total.
__global__ void scanB_kernel(int nblk, int n) {
    int v = (threadIdx.x < nblk) ? g_bsum[threadIdx.x] : 0;
    int inc = block_incl_scan(v);
    if (threadIdx.x < nblk) g_bsum[threadIdx.x] = inc - v;
    if (threadIdx.x == SCAN_B - 1) g_off[n] = inc;
}

// Pass C: add block offsets; mirror into scatter cursors.
__global__ void scanC_kernel(int n) {
    int i = blockIdx.x * SCAN_B + threadIdx.x;
    if (i < n) {
        int o = g_off[i] + g_bsum[blockIdx.x];
        g_off[i] = o;
        g_cur[i] = o;
    }
}

__global__ void scatter_kernel(const int* __restrict__ src,
                               const int* __restrict__ dst,
                               const float* __restrict__ w, int n_edges) {
    int e = blockIdx.x * blockDim.x + threadIdx.x;
    if (e >= n_edges) return;
    int d = dst[e];
    int pos = atomicAdd(&g_cur[d], 1);
    g_edge[pos] = make_int2(src[e], __float_as_int(w[e]));
}

// Row-gather accumulate for one (node, c) slice. Returns w-weighted sum of
// x[src] float4 slices over the node's CSR edge range.
__device__ __forceinline__ float4 row_gather(const float* __restrict__ x,
                                             int node, int c) {
    int beg = g_off[node];
    int end = g_off[node + 1];
    float4 a = make_float4(0.f, 0.f, 0.f, 0.f);
    int i = beg;
    for (; i + 2 <= end; i += 2) {         // 2x unroll for gather MLP
        int2 p0 = g_edge[i];
        int2 p1 = g_edge[i + 1];
        float4 v0 = *(const float4*)(x + (size_t)p0.x * D + c);
        float4 v1 = *(const float4*)(x + (size_t)p1.x * D + c);
        float w0 = __int_as_float(p0.y);
        float w1 = __int_as_float(p1.y);
        a.x += w0 * v0.x + w1 * v1.x;
        a.y += w0 * v0.y + w1 * v1.y;
        a.z += w0 * v0.z + w1 * v1.z;
        a.w += w0 * v0.w + w1 * v1.w;
    }
    if (i < end) {
        int2 p = g_edge[i];
        float4 v = *(const float4*)(x + (size_t)p.x * D + c);
        float ww = __int_as_float(p.y);
        a.x += ww * v.x; a.y += ww * v.y; a.z += ww * v.z; a.w += ww * v.w;
    }
    return a;
}

// Dense CSR SpMM over all nodes. flip=0: g_x -> g_y; flip=1: g_y -> g_x.
__global__ void spmm_dense_kernel(int n_nodes, int flip) {
    const float* __restrict__ x = flip ? g_y : g_x;
    float*                    y = flip ? g_x : g_y;
    int t = blockIdx.x * blockDim.x + threadIdx.x;
    int node = t >> 4;
    if (node >= n_nodes) return;
    int c = (t & 15) << 2;
    float4 a = row_gather(x, node, c);
    *(float4*)(y + (size_t)node * D + c) = a;   // full overwrite
}

// Sparse-output SpMM (layer 3): g_x (x2) -> g_b3, only rows in the sampled
// node list (users then items+n_users). Duplicate rows write identical data.
__global__ void spmm_list_kernel(const int* __restrict__ users,
                                 const int* __restrict__ items,
                                 int B, int n_users) {
    int t = blockIdx.x * blockDim.x + threadIdx.x;
    int li = t >> 4;
    if (li >= 2 * B) return;
    int node = (li < B) ? users[li] : n_users + items[li - B];
    int c = (t & 15) << 2;
    float4 a = row_gather(g_x, node, c);
    *(float4*)(g_b3 + (size_t)node * D + c) = a;
}

// One warp per (user, item) pair. Each side's final row = (x0+x1+x2+x3)/4,
// summed on the fly from ue/ie, g_y(x1), g_x(x2), g_b3(x3). 1/16 folded in.
__global__ void score_kernel(const float* __restrict__ ue,
                             const float* __restrict__ ie,
                             const int* __restrict__ users,
                             const int* __restrict__ items,
                             float* __restrict__ out, int B, int n_users) {
    int g    = blockIdx.x * blockDim.x + threadIdx.x;
    int pair = g >> 5;
    int lane = threadIdx.x & 31;
    if (pair >= B) return;
    int un = users[pair];
    int in = items[pair];
    int ir = n_users + in;
    size_t uo = (size_t)un * D;
    size_t io = (size_t)ir * D;
    float2 u0 = ((const float2*)(ue + uo))[lane];
    float2 u1 = ((const float2*)(g_y + uo))[lane];
    float2 u2 = ((const float2*)(g_x + uo))[lane];
    float2 u3 = ((const float2*)(g_b3 + uo))[lane];
    float2 v0 = ((const float2*)(ie + (size_t)in * D))[lane];
    float2 v1 = ((const float2*)(g_y + io))[lane];
    float2 v2 = ((const float2*)(g_x + io))[lane];
    float2 v3 = ((const float2*)(g_b3 + io))[lane];
    float ux = u0.x + u1.x + u2.x + u3.x;
    float uy = u0.y + u1.y + u2.y + u3.y;
    float vx = v0.x + v1.x + v2.x + v3.x;
    float vy = v0.y + v1.y + v2.y + v3.y;
    float s = ux * vx + uy * vy;
    #pragma unroll
    for (int o = 16; o; o >>= 1) s += __shfl_xor_sync(0xffffffffu, s, o);
    if (lane == 0) out[pair] = s * (1.0f / 16.0f);
}

extern "C" void kernel_launch(void* const* d_in, const int* in_sizes, int n_in,
                              void* d_out, int out_size) {
    const float* ue    = (const float*)d_in[0];
    const float* ie    = (const float*)d_in[1];
    const int*   esrc  = (const int*)  d_in[2];
    const int*   edst  = (const int*)  d_in[3];
    const float* ew    = (const float*)d_in[4];
    const int*   users = (const int*)  d_in[5];
    const int*   items = (const int*)  d_in[6];

    int n_user_f  = in_sizes[0];
    int n_item_f  = in_sizes[1];
    int n_edges   = in_sizes[2];
    int B         = in_sizes[5];
    int n_total_f = n_user_f + n_item_f;
    int n_users   = n_user_f / D;
    int n_nodes   = n_total_f / D;
    int n4        = n_total_f >> 2;
    int nblk      = (n_nodes + SCAN_B - 1) / SCAN_B;

    zero_cnt_kernel<<<(n_nodes + 255) / 256, 256>>>(n_nodes);
    init_kernel<<<(n4 + 255) / 256, 256>>>(ue, ie, n_user_f, n4);
    hist_kernel<<<(n_edges + 255) / 256, 256>>>(edst, n_edges);
    scanA_kernel<<<nblk, SCAN_B>>>(n_nodes);
    scanB_kernel<<<1, SCAN_B>>>(nblk, n_nodes);
    scanC_kernel<<<nblk, SCAN_B>>>(n_nodes);
    scatter_kernel<<<(n_edges + 255) / 256, 256>>>(esrc, edst, ew, n_edges);

    long long td = (long long)n_nodes * 16;
    int gd = (int)((td + 255) / 256);
    // Layer 1: x1 = A x0   (g_x -> g_y)
    spmm_dense_kernel<<<gd, 256>>>(n_nodes, 0);
    // Layer 2: x2 = A x1   (g_y -> g_x; x0 scratch copy no longer needed)
    spmm_dense_kernel<<<gd, 256>>>(n_nodes, 1);
    // Layer 3: x3 = A x2 only at sampled rows (g_x -> g_b3)
    int gl = (2 * B * 16 + 255) / 256;
    spmm_list_kernel<<<gl, 256>>>(users, items, B, n_users);

    score_kernel<<<(B * 32 + 255) / 256, 256>>>(ue, ie, users, items,
                                                (float*)d_out, B, n_users);
}